// round 2
// baseline (speedup 1.0000x reference)
#include <cuda_runtime.h>
#include <math.h>

// Problem constants
#define B_  16
#define S_  1024
#define L_  512
#define D_  1024
#define H_  8
#define DH_ 128
#define WD_ 256
#define CK_ (D_ + WD_)     // 1280, concat width
#define MAXN 128           // cap on allowed positions per query (E[n]~3)

// ---------------- scratch (static device globals; no allocation) -------------
__device__ float gK[B_ * S_ * D_];          // 64 MB
__device__ float gV[B_ * S_ * D_];          // 64 MB
__device__ float gQ[B_ * L_ * D_];          // 32 MB
__device__ float gCtx[B_ * L_ * D_];        // 32 MB
__device__ float gConcat[B_ * L_ * CK_];    // 40 MB  [sem_out | type_vec]
__device__ int   gToSem[B_ * L_];           // int32 copies of the index inputs
__device__ int   gToSemType[B_ * L_];
__device__ int   gSemSyn[B_ * S_];

// ---------------------------------------------------------------------------
// Index conversion with dtype sniffing. src may be int32[n] or int64[n]
// (little-endian, values < 2^31). For int64, every odd 32-bit word is 0;
// for int32 random data the OR of odd words is nonzero (P_fail ~ 2^-4000).
// One block per buffer; deterministic; graph-capturable.
// ---------------------------------------------------------------------------
__global__ void __launch_bounds__(256) conv_idx_kernel(
    const unsigned int* __restrict__ src, int n, int* __restrict__ dst)
{
    __shared__ unsigned s_or[8];
    __shared__ int s_is64;
    const int tid = threadIdx.x;

    // OR of odd 32-bit words among the first n words (safe for both layouts).
    unsigned acc = 0;
    for (int i = tid; 2 * i + 1 < n; i += 256) acc |= src[2 * i + 1];
    #pragma unroll
    for (int off = 16; off > 0; off >>= 1)
        acc |= __shfl_xor_sync(0xFFFFFFFFu, acc, off);
    if ((tid & 31) == 0) s_or[tid >> 5] = acc;
    __syncthreads();
    if (tid == 0) {
        unsigned t = 0;
        #pragma unroll
        for (int i = 0; i < 8; i++) t |= s_or[i];
        s_is64 = (t == 0u);   // all odd words zero -> int64 layout
    }
    __syncthreads();
    const int is64 = s_is64;

    for (int i = tid; i < n; i += 256)
        dst[i] = (int)(is64 ? src[2 * i] : src[i]);
}

// ---------------------------------------------------------------------------
// GEMM: C[M,N] = (A[M,K] @ W[N,K]^T + bias[N]) * alpha
// BM=128, BN=64, BK=16, 256 threads, 8x4 per-thread microtile.
// gather != nullptr: A row m reads encoder row (m/512)*1024 + gather[m].
// C2 != nullptr: also write row (m/512)*513 + (m%512) + 1 of C2 (ld 1024).
// All dims here are multiples of the tile sizes (no bounds checks).
// ---------------------------------------------------------------------------
__global__ void __launch_bounds__(256) gemm_kernel(
    const float* __restrict__ A, const float* __restrict__ W,
    const float* __restrict__ bias, float* __restrict__ C,
    int K, int lda, int ldc,
    const int* __restrict__ gather, float alpha, float* __restrict__ C2)
{
    __shared__ float As[16][128];
    __shared__ float Ws[16][64];

    const int bm = blockIdx.y * 128;
    const int bn = blockIdx.x * 64;
    const int tid = threadIdx.x;

    // A-load mapping: 2 float4 per thread (rows ar0, ar0+64; k offset ak)
    const int ar0 = tid >> 2;          // 0..63
    const int ar1 = ar0 + 64;          // 64..127
    const int ak  = (tid & 3) << 2;    // 0,4,8,12

    long arow0, arow1;
    {
        int m0 = bm + ar0, m1 = bm + ar1;
        if (gather) {
            arow0 = (long)((m0 >> 9) * S_ + gather[m0]) * lda;
            arow1 = (long)((m1 >> 9) * S_ + gather[m1]) * lda;
        } else {
            arow0 = (long)m0 * lda;
            arow1 = (long)m1 * lda;
        }
    }
    const int  wr   = tid >> 2;                 // 0..63
    const long wrow = (long)(bn + wr) * K;

    const int tm = (tid >> 4) << 3;    // 0..120
    const int tn = (tid & 15) << 2;    // 0..60

    float acc[8][4];
    #pragma unroll
    for (int i = 0; i < 8; i++)
        #pragma unroll
        for (int j = 0; j < 4; j++) acc[i][j] = 0.f;

    for (int k0 = 0; k0 < K; k0 += 16) {
        float4 a0 = *(const float4*)(A + arow0 + k0 + ak);
        float4 a1 = *(const float4*)(A + arow1 + k0 + ak);
        float4 w0 = *(const float4*)(W + wrow  + k0 + ak);
        __syncthreads();
        As[ak + 0][ar0] = a0.x; As[ak + 1][ar0] = a0.y;
        As[ak + 2][ar0] = a0.z; As[ak + 3][ar0] = a0.w;
        As[ak + 0][ar1] = a1.x; As[ak + 1][ar1] = a1.y;
        As[ak + 2][ar1] = a1.z; As[ak + 3][ar1] = a1.w;
        Ws[ak + 0][wr]  = w0.x; Ws[ak + 1][wr]  = w0.y;
        Ws[ak + 2][wr]  = w0.z; Ws[ak + 3][wr]  = w0.w;
        __syncthreads();
        #pragma unroll
        for (int kk = 0; kk < 16; kk++) {
            float4 af0 = *(const float4*)&As[kk][tm];
            float4 af1 = *(const float4*)&As[kk][tm + 4];
            float4 wf  = *(const float4*)&Ws[kk][tn];
            float a[8] = {af0.x, af0.y, af0.z, af0.w, af1.x, af1.y, af1.z, af1.w};
            float w[4] = {wf.x, wf.y, wf.z, wf.w};
            #pragma unroll
            for (int i = 0; i < 8; i++)
                #pragma unroll
                for (int j = 0; j < 4; j++)
                    acc[i][j] += a[i] * w[j];
        }
    }

    float4 b4 = *(const float4*)(bias + bn + tn);
    #pragma unroll
    for (int i = 0; i < 8; i++) {
        int m = bm + tm + i;
        float4 o;
        o.x = (acc[i][0] + b4.x) * alpha;
        o.y = (acc[i][1] + b4.y) * alpha;
        o.z = (acc[i][2] + b4.z) * alpha;
        o.w = (acc[i][3] + b4.w) * alpha;
        *(float4*)(C + (long)m * ldc + bn + tn) = o;
        if (C2) {
            long r2 = (long)((m >> 9) * (L_ + 1) + (m & (L_ - 1)) + 1);
            *(float4*)(C2 + r2 * D_ + bn + tn) = o;
        }
    }
}

// ---------------------------------------------------------------------------
// Sparse masked attention. One block per (b,l), 256 threads = 8 warps = heads.
// allow[b,l,s] = (sem_syn[b,s] == l+1) | (s == to_sem[b,l]); softmax over the
// allowed set is exactly the reference masked softmax. n ~ 3 on average.
// List built deterministically (ordered ballot scan by warp 0).
// ---------------------------------------------------------------------------
__global__ void __launch_bounds__(256) attn_kernel(
    const float* __restrict__ Q, const float* __restrict__ Kb,
    const float* __restrict__ Vb,
    const int* __restrict__ sem_syn, const int* __restrict__ to_sem,
    float* __restrict__ Ctx)
{
    const int bl = blockIdx.x;           // b*512 + l
    const int b  = bl >> 9;
    const int l  = bl & (L_ - 1);

    __shared__ int   s_list[MAXN];
    __shared__ int   s_n;
    __shared__ float s_scores[H_][MAXN];

    const int tid  = threadIdx.x;
    const int w    = tid >> 5;           // head
    const int lane = tid & 31;

    if (w == 0) {
        int cnt = 0;
        const int* syn = sem_syn + b * S_;
        #pragma unroll 4
        for (int c = 0; c < S_ / 32; c++) {
            int s = c * 32 + lane;
            int ok = (syn[s] == l + 1);
            unsigned msk = __ballot_sync(0xFFFFFFFFu, ok);
            if (ok) {
                int pos = cnt + __popc(msk & ((1u << lane) - 1));
                if (pos < MAXN) s_list[pos] = s;
            }
            cnt += __popc(msk);
        }
        if (lane == 0) {
            int sp = to_sem[bl];
            if (syn[sp] != l + 1) {
                if (cnt < MAXN) s_list[cnt] = sp;
                cnt++;
            }
            s_n = (cnt < MAXN) ? cnt : MAXN;
        }
    }
    __syncthreads();
    const int n = s_n;

    const long hoff = (long)w * DH_ + lane * 4;
    float4 q = *(const float4*)(Q + (long)bl * D_ + hoff);

    for (int i = 0; i < n; i++) {
        int s = s_list[i];
        float4 k4 = *(const float4*)(Kb + ((long)(b * S_ + s)) * D_ + hoff);
        float d = q.x * k4.x + q.y * k4.y + q.z * k4.z + q.w * k4.w;
        #pragma unroll
        for (int off = 16; off > 0; off >>= 1)
            d += __shfl_xor_sync(0xFFFFFFFFu, d, off);
        if (lane == 0) s_scores[w][i] = d;
    }
    __syncwarp();

    float mx = -1e30f;
    for (int i = 0; i < n; i++) mx = fmaxf(mx, s_scores[w][i]);
    float sum = 0.f;
    for (int i = 0; i < n; i++) sum += expf(s_scores[w][i] - mx);
    float inv = 1.f / sum;

    float4 acc = make_float4(0.f, 0.f, 0.f, 0.f);
    for (int i = 0; i < n; i++) {
        float p = expf(s_scores[w][i] - mx) * inv;
        float4 v4 = *(const float4*)(Vb + ((long)(b * S_ + s_list[i])) * D_ + hoff);
        acc.x += p * v4.x; acc.y += p * v4.y;
        acc.z += p * v4.z; acc.w += p * v4.w;
    }
    *(float4*)(Ctx + (long)bl * D_ + hoff) = acc;
}

// type_vec: concat[:, 1024:1280] = type_emb[to_sem_type]
__global__ void type_copy_kernel(const int* __restrict__ to_sem_type,
                                 const float* __restrict__ type_emb,
                                 float* __restrict__ concat)
{
    int m = blockIdx.x;        // 0..8191
    int j = threadIdx.x;       // 0..255
    concat[(long)m * CK_ + D_ + j] = type_emb[(long)to_sem_type[m] * WD_ + j];
}

// out2[b, 0, :] = bias_root
__global__ void root_fill_kernel(const float* __restrict__ bias_root,
                                 float* __restrict__ out2)
{
    int idx = blockIdx.x * 256 + threadIdx.x;   // 16*1024
    int b = idx >> 10, d = idx & (D_ - 1);
    out2[(long)b * (L_ + 1) * D_ + d] = bias_root[d];
}

// ---------------------------------------------------------------------------
extern "C" void kernel_launch(void* const* d_in, const int* in_sizes, int n_in,
                              void* d_out, int out_size)
{
    const float* enc        = (const float*)d_in[0];
    const void*  to_sem_raw = d_in[1];
    const void*  typ_raw    = d_in[2];
    const void*  syn_raw    = d_in[3];
    const float* wq = (const float*)d_in[4];  const float* bq = (const float*)d_in[5];
    const float* wk = (const float*)d_in[6];  const float* bk = (const float*)d_in[7];
    const float* wv = (const float*)d_in[8];  const float* bv = (const float*)d_in[9];
    const float* wo = (const float*)d_in[10]; const float* bo = (const float*)d_in[11];
    const float* type_emb  = (const float*)d_in[12];
    const float* w_proj    = (const float*)d_in[13];
    const float* b_proj    = (const float*)d_in[14];
    const float* bias_root = (const float*)d_in[15];

    float* out1 = (float*)d_out;                         // embedding [B,L,D]
    float* out2 = out1 + (long)B_ * L_ * D_;             // [root; embedding] [B,L+1,D]

    float *pK, *pV, *pQ, *pCtx, *pCat;
    int *pToSem, *pToSemType, *pSemSyn;
    cudaGetSymbolAddress((void**)&pK,   gK);
    cudaGetSymbolAddress((void**)&pV,   gV);
    cudaGetSymbolAddress((void**)&pQ,   gQ);
    cudaGetSymbolAddress((void**)&pCtx, gCtx);
    cudaGetSymbolAddress((void**)&pCat, gConcat);
    cudaGetSymbolAddress((void**)&pToSem,     gToSem);
    cudaGetSymbolAddress((void**)&pToSemType, gToSemType);
    cudaGetSymbolAddress((void**)&pSemSyn,    gSemSyn);

    const float qscale = 0.08838834764831845f;   // DH^-0.5

    dim3 blk(256);

    // Normalize index dtypes (int32 or int64) into int32 scratch.
    conv_idx_kernel<<<1, blk>>>((const unsigned int*)to_sem_raw, B_ * L_, pToSem);
    conv_idx_kernel<<<1, blk>>>((const unsigned int*)typ_raw,    B_ * L_, pToSemType);
    conv_idx_kernel<<<1, blk>>>((const unsigned int*)syn_raw,    B_ * S_, pSemSyn);

    // K/V projections: [16384,1024] @ [1024,1024]^T
    gemm_kernel<<<dim3(D_ / 64, (B_ * S_) / 128), blk>>>(
        enc, wk, bk, pK, D_, D_, D_, nullptr, 1.f, nullptr);
    gemm_kernel<<<dim3(D_ / 64, (B_ * S_) / 128), blk>>>(
        enc, wv, bv, pV, D_, D_, D_, nullptr, 1.f, nullptr);

    // Q projection with fused gather of sem_vec rows, scaled by DH^-0.5
    gemm_kernel<<<dim3(D_ / 64, (B_ * L_) / 128), blk>>>(
        enc, wq, bq, pQ, D_, D_, D_, pToSem, qscale, nullptr);

    // Sparse masked attention -> ctx
    attn_kernel<<<B_ * L_, blk>>>(pQ, pK, pV, pSemSyn, pToSem, pCtx);

    // O projection, written directly into concat buffer cols [0,1024)
    gemm_kernel<<<dim3(D_ / 64, (B_ * L_) / 128), blk>>>(
        pCtx, wo, bo, pCat, D_, D_, CK_, nullptr, 1.f, nullptr);

    // type embedding -> concat cols [1024,1280)
    type_copy_kernel<<<B_ * L_, blk>>>(pToSemType, type_emb, pCat);

    // Final projection: [8192,1280] @ [1024,1280]^T -> both outputs
    gemm_kernel<<<dim3(D_ / 64, (B_ * L_) / 128), blk>>>(
        pCat, w_proj, b_proj, out1, CK_, CK_, D_, nullptr, 1.f, out2);

    // root rows of out2
    root_fill_kernel<<<(B_ * D_) / 256, blk>>>(bias_root, out2);
}

// round 7
// speedup vs baseline: 1.9933x; 1.9933x over previous
#include <cuda_runtime.h>
#include <cuda_bf16.h>
#include <math.h>
#include <stdint.h>

// Problem constants
#define B_  16
#define S_  1024
#define L_  512
#define D_  1024
#define H_  8
#define DH_ 128
#define WD_ 256
#define CK_ (D_ + WD_)     // 1280
#define MAXN 128

// ---------------- scratch ----------------------------------------------------
__device__ float gK[B_ * S_ * D_];
__device__ float gV[B_ * S_ * D_];
__device__ float gQ[B_ * L_ * D_];
__device__ float gCtx[B_ * L_ * D_];
__device__ float gConcat[B_ * L_ * CK_];
__device__ int   gToSem[B_ * L_];
__device__ int   gToSemType[B_ * L_];
__device__ int   gSemSyn[B_ * S_];

// ---------------- helpers ----------------------------------------------------
__device__ __forceinline__ uint32_t smem_u32(const void* p) {
    uint32_t a;
    asm("{ .reg .u64 t; cvta.to.shared.u64 t, %1; cvt.u32.u64 %0, t; }" : "=r"(a) : "l"(p));
    return a;
}

__device__ __forceinline__ void ldsm4(uint32_t* r, uint32_t addr) {
    asm volatile("ldmatrix.sync.aligned.m8n8.x4.shared.b16 {%0,%1,%2,%3}, [%4];"
        : "=r"(r[0]), "=r"(r[1]), "=r"(r[2]), "=r"(r[3]) : "r"(addr));
}

__device__ __forceinline__ void mma_bf16(float* d, const uint32_t* a, const uint32_t* b) {
    asm volatile(
        "mma.sync.aligned.m16n8k16.row.col.f32.bf16.bf16.f32 "
        "{%0,%1,%2,%3}, {%4,%5,%6,%7}, {%8,%9}, {%0,%1,%2,%3};"
        : "+f"(d[0]), "+f"(d[1]), "+f"(d[2]), "+f"(d[3])
        : "r"(a[0]), "r"(a[1]), "r"(a[2]), "r"(a[3]), "r"(b[0]), "r"(b[1]));
}

// split 8 floats -> 8 bf16 hi + 8 bf16 lo (x = hi + lo)
__device__ __forceinline__ void split8(float4 a, float4 b, uint4& hi, uint4& lo) {
    __nv_bfloat162 h0 = __float22bfloat162_rn(make_float2(a.x, a.y));
    __nv_bfloat162 h1 = __float22bfloat162_rn(make_float2(a.z, a.w));
    __nv_bfloat162 h2 = __float22bfloat162_rn(make_float2(b.x, b.y));
    __nv_bfloat162 h3 = __float22bfloat162_rn(make_float2(b.z, b.w));
    float2 f0 = __bfloat1622float2(h0), f1 = __bfloat1622float2(h1);
    float2 f2 = __bfloat1622float2(h2), f3 = __bfloat1622float2(h3);
    __nv_bfloat162 l0 = __float22bfloat162_rn(make_float2(a.x - f0.x, a.y - f0.y));
    __nv_bfloat162 l1 = __float22bfloat162_rn(make_float2(a.z - f1.x, a.w - f1.y));
    __nv_bfloat162 l2 = __float22bfloat162_rn(make_float2(b.x - f2.x, b.y - f2.y));
    __nv_bfloat162 l3 = __float22bfloat162_rn(make_float2(b.z - f3.x, b.w - f3.y));
    hi.x = *(uint32_t*)&h0; hi.y = *(uint32_t*)&h1;
    hi.z = *(uint32_t*)&h2; hi.w = *(uint32_t*)&h3;
    lo.x = *(uint32_t*)&l0; lo.y = *(uint32_t*)&l1;
    lo.z = *(uint32_t*)&l2; lo.w = *(uint32_t*)&l3;
}

// ---------------------------------------------------------------------------
// bf16x3 HMMA GEMM: C[M,N] = (A[M,K] @ W[N,K]^T + bias) * alpha
// BM=128, BN=128, BK=16, 256 threads, 8 warps (2 in M x 4 in N, 64x32 tiles).
// STATIC smem (48KB exactly) — no dynamic smem, no cudaFuncSetAttribute.
// smem rows of 16 bf16 at 48B stride (conflict-free ldmatrix);
// planes Ah|Al|Wh|Wl per stage, 2 stages, plain __syncthreads pipeline.
// gather: A row m reads encoder row (m>>9)*1024 + gather[m].
// C2: also write row (m>>9)*513 + (m&511) + 1, ld=1024.
// ---------------------------------------------------------------------------
#define AST     48                       // smem row stride (bytes)
#define PLANE   (128 * AST)              // 6144 B
#define STAGE   (4 * PLANE)              // 24576 B : Ah,Al,Wh,Wl
#define SMEM_TOTAL (2 * STAGE)           // 49152 B (static limit)

__global__ void __launch_bounds__(256) gemm_mma(
    const float* __restrict__ A, const float* __restrict__ W,
    const float* __restrict__ bias, float* __restrict__ C,
    int K, int lda, int ldc,
    const int* __restrict__ gather, float alpha, float* __restrict__ C2)
{
    __shared__ char smem[SMEM_TOTAL];
    const uint32_t sb = smem_u32(smem);
    const int tid = threadIdx.x, wid = tid >> 5, lane = tid & 31;
    const int bm = blockIdx.y * 128, bn = blockIdx.x * 128;
    const int warp_m = wid >> 2;          // 0..1 -> 64-row slice
    const int warp_n = wid & 3;           // 0..3 -> 32-col slice

    // ---- writer mapping: row = tid>>1 (0..127), k-half = tid&1 -------------
    const int wrow = tid >> 1;
    const int wkh  = tid & 1;
    long aoff;
    {
        int m = bm + wrow;
        aoff = gather ? ((long)((m >> 9) * S_ + gather[m]) * lda)
                      : ((long)m * lda);
    }
    const float* Ap = A + aoff + wkh * 8;
    const float* Wp = W + (long)(bn + wrow) * K + wkh * 8;
    const uint32_t wst = (uint32_t)(wrow * AST + wkh * 16);

    // ---- ldmatrix lane addresses (offsets within a stage) ------------------
    // A: matrices (m0-7,k0-7),(m8-15,k0-7),(m0-7,k8-15),(m8-15,k8-15)
    uint32_t a_addr[4];
    {
        int r  = (lane & 7) + ((lane >> 3) & 1) * 8;
        int kh = (lane >> 4) & 1;
        #pragma unroll
        for (int mt = 0; mt < 4; mt++)
            a_addr[mt] = (uint32_t)((warp_m * 64 + mt * 16 + r) * AST + kh * 16);
    }
    // B: matrices (n0-7,k0-7),(n0-7,k8-15),(n8-15,k0-7),(n8-15,k8-15)
    uint32_t b_addr[2];
    {
        int r  = (lane & 7) + ((lane >> 4) & 1) * 8;
        int kh = (lane >> 3) & 1;
        #pragma unroll
        for (int np = 0; np < 2; np++)
            b_addr[np] = (uint32_t)(2 * PLANE + (warp_n * 32 + np * 16 + r) * AST + kh * 16);
    }

    float acc[4][4][4];
    #pragma unroll
    for (int i = 0; i < 4; i++)
        #pragma unroll
        for (int j = 0; j < 4; j++)
            #pragma unroll
            for (int k = 0; k < 4; k++) acc[i][j][k] = 0.f;

    const int nch = K / 16;

    // ---- prologue: chunk 0 -> stage 0 --------------------------------------
    {
        float4 a0 = *(const float4*)(Ap);
        float4 a1 = *(const float4*)(Ap + 4);
        float4 w0 = *(const float4*)(Wp);
        float4 w1 = *(const float4*)(Wp + 4);
        uint4 hi, lo;
        split8(a0, a1, hi, lo);
        *(uint4*)(smem + wst)          = hi;
        *(uint4*)(smem + PLANE + wst)  = lo;
        split8(w0, w1, hi, lo);
        *(uint4*)(smem + 2 * PLANE + wst) = hi;
        *(uint4*)(smem + 3 * PLANE + wst) = lo;
    }
    __syncthreads();

    for (int c = 0; c < nch; c++) {
        // prefetch next chunk globals
        float4 pa0, pa1, pw0, pw1;
        if (c + 1 < nch) {
            pa0 = *(const float4*)(Ap + (c + 1) * 16);
            pa1 = *(const float4*)(Ap + (c + 1) * 16 + 4);
            pw0 = *(const float4*)(Wp + (c + 1) * 16);
            pw1 = *(const float4*)(Wp + (c + 1) * 16 + 4);
        }

        // compute from stage c&1
        const uint32_t st = sb + (c & 1) * STAGE;
        uint32_t ah[4][4], al[4][4], bh[4][2], bl[4][2];
        #pragma unroll
        for (int mt = 0; mt < 4; mt++) {
            ldsm4(ah[mt], st + a_addr[mt]);
            ldsm4(al[mt], st + a_addr[mt] + PLANE);
        }
        #pragma unroll
        for (int np = 0; np < 2; np++) {
            uint32_t r[4];
            ldsm4(r, st + b_addr[np]);
            bh[2 * np][0] = r[0]; bh[2 * np][1] = r[1];
            bh[2 * np + 1][0] = r[2]; bh[2 * np + 1][1] = r[3];
            ldsm4(r, st + b_addr[np] + PLANE);
            bl[2 * np][0] = r[0]; bl[2 * np][1] = r[1];
            bl[2 * np + 1][0] = r[2]; bl[2 * np + 1][1] = r[3];
        }
        #pragma unroll
        for (int mt = 0; mt < 4; mt++)
            #pragma unroll
            for (int nt = 0; nt < 4; nt++) {
                mma_bf16(acc[mt][nt], ah[mt], bh[nt]);
                mma_bf16(acc[mt][nt], ah[mt], bl[nt]);
                mma_bf16(acc[mt][nt], al[mt], bh[nt]);
            }

        // store next chunk into the other stage
        if (c + 1 < nch) {
            char* stn = smem + ((c + 1) & 1) * STAGE;
            uint4 hi, lo;
            split8(pa0, pa1, hi, lo);
            *(uint4*)(stn + wst)         = hi;
            *(uint4*)(stn + PLANE + wst) = lo;
            split8(pw0, pw1, hi, lo);
            *(uint4*)(stn + 2 * PLANE + wst) = hi;
            *(uint4*)(stn + 3 * PLANE + wst) = lo;
        }
        __syncthreads();
    }

    // ---- epilogue ----------------------------------------------------------
    const int mrow = (lane >> 2);
    const int ncol = 2 * (lane & 3);
    #pragma unroll
    for (int mt = 0; mt < 4; mt++) {
        #pragma unroll
        for (int nt = 0; nt < 4; nt++) {
            int m0 = bm + warp_m * 64 + mt * 16 + mrow;
            int n  = bn + warp_n * 32 + nt * 8 + ncol;
            float2 bb = *(const float2*)(bias + n);
            float2 o0, o1;
            o0.x = (acc[mt][nt][0] + bb.x) * alpha;
            o0.y = (acc[mt][nt][1] + bb.y) * alpha;
            o1.x = (acc[mt][nt][2] + bb.x) * alpha;
            o1.y = (acc[mt][nt][3] + bb.y) * alpha;
            *(float2*)(C + (long)m0 * ldc + n)       = o0;
            *(float2*)(C + (long)(m0 + 8) * ldc + n) = o1;
            if (C2) {
                long r0 = (long)((m0 >> 9) * (L_ + 1) + (m0 & (L_ - 1)) + 1);
                int  m1 = m0 + 8;
                long r1 = (long)((m1 >> 9) * (L_ + 1) + (m1 & (L_ - 1)) + 1);
                *(float2*)(C2 + r0 * D_ + n) = o0;
                *(float2*)(C2 + r1 * D_ + n) = o1;
            }
        }
    }
}

// ---------------------------------------------------------------------------
// Index conversion with dtype sniffing (int32 or int64 LE).
// ---------------------------------------------------------------------------
__global__ void __launch_bounds__(256) conv_idx_kernel(
    const unsigned int* __restrict__ src, int n, int* __restrict__ dst)
{
    __shared__ unsigned s_or[8];
    __shared__ int s_is64;
    const int tid = threadIdx.x;
    unsigned acc = 0;
    for (int i = tid; 2 * i + 1 < n; i += 256) acc |= src[2 * i + 1];
    #pragma unroll
    for (int off = 16; off > 0; off >>= 1)
        acc |= __shfl_xor_sync(0xFFFFFFFFu, acc, off);
    if ((tid & 31) == 0) s_or[tid >> 5] = acc;
    __syncthreads();
    if (tid == 0) {
        unsigned t = 0;
        #pragma unroll
        for (int i = 0; i < 8; i++) t |= s_or[i];
        s_is64 = (t == 0u);
    }
    __syncthreads();
    const int is64 = s_is64;
    for (int i = tid; i < n; i += 256)
        dst[i] = (int)(is64 ? src[2 * i] : src[i]);
}

// ---------------------------------------------------------------------------
// Sparse masked attention (proven in R2).
// ---------------------------------------------------------------------------
__global__ void __launch_bounds__(256) attn_kernel(
    const float* __restrict__ Q, const float* __restrict__ Kb,
    const float* __restrict__ Vb,
    const int* __restrict__ sem_syn, const int* __restrict__ to_sem,
    float* __restrict__ Ctx)
{
    const int bl = blockIdx.x;
    const int b  = bl >> 9;
    const int l  = bl & (L_ - 1);

    __shared__ int   s_list[MAXN];
    __shared__ int   s_n;
    __shared__ float s_scores[H_][MAXN];

    const int tid  = threadIdx.x;
    const int w    = tid >> 5;
    const int lane = tid & 31;

    if (w == 0) {
        int cnt = 0;
        const int* syn = sem_syn + b * S_;
        #pragma unroll 4
        for (int c = 0; c < S_ / 32; c++) {
            int s = c * 32 + lane;
            int ok = (syn[s] == l + 1);
            unsigned msk = __ballot_sync(0xFFFFFFFFu, ok);
            if (ok) {
                int pos = cnt + __popc(msk & ((1u << lane) - 1));
                if (pos < MAXN) s_list[pos] = s;
            }
            cnt += __popc(msk);
        }
        if (lane == 0) {
            int sp = to_sem[bl];
            if (syn[sp] != l + 1) {
                if (cnt < MAXN) s_list[cnt] = sp;
                cnt++;
            }
            s_n = (cnt < MAXN) ? cnt : MAXN;
        }
    }
    __syncthreads();
    const int n = s_n;

    const long hoff = (long)w * DH_ + lane * 4;
    float4 q = *(const float4*)(Q + (long)bl * D_ + hoff);

    for (int i = 0; i < n; i++) {
        int s = s_list[i];
        float4 k4 = *(const float4*)(Kb + ((long)(b * S_ + s)) * D_ + hoff);
        float d = q.x * k4.x + q.y * k4.y + q.z * k4.z + q.w * k4.w;
        #pragma unroll
        for (int off = 16; off > 0; off >>= 1)
            d += __shfl_xor_sync(0xFFFFFFFFu, d, off);
        if (lane == 0) s_scores[w][i] = d;
    }
    __syncwarp();

    float mx = -1e30f;
    for (int i = 0; i < n; i++) mx = fmaxf(mx, s_scores[w][i]);
    float sum = 0.f;
    for (int i = 0; i < n; i++) sum += expf(s_scores[w][i] - mx);
    float inv = 1.f / sum;

    float4 acc = make_float4(0.f, 0.f, 0.f, 0.f);
    for (int i = 0; i < n; i++) {
        float p = expf(s_scores[w][i] - mx) * inv;
        float4 v4 = *(const float4*)(Vb + ((long)(b * S_ + s_list[i])) * D_ + hoff);
        acc.x += p * v4.x; acc.y += p * v4.y;
        acc.z += p * v4.z; acc.w += p * v4.w;
    }
    *(float4*)(Ctx + (long)bl * D_ + hoff) = acc;
}

__global__ void type_copy_kernel(const int* __restrict__ to_sem_type,
                                 const float* __restrict__ type_emb,
                                 float* __restrict__ concat)
{
    int m = blockIdx.x;
    int j = threadIdx.x;
    concat[(long)m * CK_ + D_ + j] = type_emb[(long)to_sem_type[m] * WD_ + j];
}

__global__ void root_fill_kernel(const float* __restrict__ bias_root,
                                 float* __restrict__ out2)
{
    int idx = blockIdx.x * 256 + threadIdx.x;
    int b = idx >> 10, d = idx & (D_ - 1);
    out2[(long)b * (L_ + 1) * D_ + d] = bias_root[d];
}

// ---------------------------------------------------------------------------
extern "C" void kernel_launch(void* const* d_in, const int* in_sizes, int n_in,
                              void* d_out, int out_size)
{
    const float* enc        = (const float*)d_in[0];
    const void*  to_sem_raw = d_in[1];
    const void*  typ_raw    = d_in[2];
    const void*  syn_raw    = d_in[3];
    const float* wq = (const float*)d_in[4];  const float* bq = (const float*)d_in[5];
    const float* wk = (const float*)d_in[6];  const float* bk = (const float*)d_in[7];
    const float* wv = (const float*)d_in[8];  const float* bv = (const float*)d_in[9];
    const float* wo = (const float*)d_in[10]; const float* bo = (const float*)d_in[11];
    const float* type_emb  = (const float*)d_in[12];
    const float* w_proj    = (const float*)d_in[13];
    const float* b_proj    = (const float*)d_in[14];
    const float* bias_root = (const float*)d_in[15];

    float* out1 = (float*)d_out;
    float* out2 = out1 + (long)B_ * L_ * D_;

    float *pK, *pV, *pQ, *pCtx, *pCat;
    int *pToSem, *pToSemType, *pSemSyn;
    cudaGetSymbolAddress((void**)&pK,   gK);
    cudaGetSymbolAddress((void**)&pV,   gV);
    cudaGetSymbolAddress((void**)&pQ,   gQ);
    cudaGetSymbolAddress((void**)&pCtx, gCtx);
    cudaGetSymbolAddress((void**)&pCat, gConcat);
    cudaGetSymbolAddress((void**)&pToSem,     gToSem);
    cudaGetSymbolAddress((void**)&pToSemType, gToSemType);
    cudaGetSymbolAddress((void**)&pSemSyn,    gSemSyn);

    const float qscale = 0.08838834764831845f;   // DH^-0.5
    dim3 blk(256);

    conv_idx_kernel<<<1, blk>>>((const unsigned int*)to_sem_raw, B_ * L_, pToSem);
    conv_idx_kernel<<<1, blk>>>((const unsigned int*)typ_raw,    B_ * L_, pToSemType);
    conv_idx_kernel<<<1, blk>>>((const unsigned int*)syn_raw,    B_ * S_, pSemSyn);

    // K/V projections: [16384,1024] @ [1024,1024]^T
    gemm_mma<<<dim3(D_ / 128, (B_ * S_) / 128), blk>>>(
        enc, wk, bk, pK, D_, D_, D_, nullptr, 1.f, nullptr);
    gemm_mma<<<dim3(D_ / 128, (B_ * S_) / 128), blk>>>(
        enc, wv, bv, pV, D_, D_, D_, nullptr, 1.f, nullptr);

    // Q projection with fused gather + scale
    gemm_mma<<<dim3(D_ / 128, (B_ * L_) / 128), blk>>>(
        enc, wq, bq, pQ, D_, D_, D_, pToSem, qscale, nullptr);

    // Sparse attention
    attn_kernel<<<B_ * L_, blk>>>(pQ, pK, pV, pSemSyn, pToSem, pCtx);

    // O projection into concat cols [0,1024)
    gemm_mma<<<dim3(D_ / 128, (B_ * L_) / 128), blk>>>(
        pCtx, wo, bo, pCat, D_, D_, CK_, nullptr, 1.f, nullptr);

    // type embedding -> concat cols [1024,1280)
    type_copy_kernel<<<B_ * L_, blk>>>(pToSemType, type_emb, pCat);

    // Final projection K=1280 -> both outputs
    gemm_mma<<<dim3(D_ / 128, (B_ * L_) / 128), blk>>>(
        pCat, w_proj, b_proj, out1, CK_, CK_, D_, nullptr, 1.f, out2);

    root_fill_kernel<<<(B_ * D_) / 256, blk>>>(bias_root, out2);
}

// round 10
// speedup vs baseline: 2.3397x; 1.1738x over previous
#include <cuda_runtime.h>
#include <cuda_bf16.h>
#include <math.h>
#include <stdint.h>

// Problem constants
#define B_  16
#define S_  1024
#define L_  512
#define D_  1024
#define H_  8
#define DH_ 128
#define WD_ 256
#define CK_ (D_ + WD_)     // 1280
#define MAXN 128

// ---------------- scratch ----------------------------------------------------
__device__ __align__(256) float gK[B_ * S_ * D_];
__device__ __align__(256) float gV[B_ * S_ * D_];
__device__ __align__(256) float gQ[B_ * L_ * D_];
__device__ __align__(256) __nv_bfloat16 gEncH[B_ * S_ * D_];
__device__ __align__(256) __nv_bfloat16 gEncL[B_ * S_ * D_];
__device__ __align__(256) __nv_bfloat16 gWkH[D_ * D_];
__device__ __align__(256) __nv_bfloat16 gWkL[D_ * D_];
__device__ __align__(256) __nv_bfloat16 gWvH[D_ * D_];
__device__ __align__(256) __nv_bfloat16 gWvL[D_ * D_];
__device__ __align__(256) __nv_bfloat16 gWqH[D_ * D_];
__device__ __align__(256) __nv_bfloat16 gWqL[D_ * D_];
__device__ __align__(256) __nv_bfloat16 gWoH[D_ * D_];
__device__ __align__(256) __nv_bfloat16 gWoL[D_ * D_];
__device__ __align__(256) __nv_bfloat16 gWpH[D_ * CK_];
__device__ __align__(256) __nv_bfloat16 gWpL[D_ * CK_];
__device__ __align__(256) __nv_bfloat16 gCtxH[B_ * L_ * D_];
__device__ __align__(256) __nv_bfloat16 gCtxL[B_ * L_ * D_];
__device__ __align__(256) __nv_bfloat16 gCatH[B_ * L_ * CK_];
__device__ __align__(256) __nv_bfloat16 gCatL[B_ * L_ * CK_];
__device__ int gToSem[B_ * L_];
__device__ int gToSemType[B_ * L_];
__device__ int gSemSyn[B_ * S_];

// ---------------- helpers ----------------------------------------------------
__device__ __forceinline__ uint32_t smem_u32(const void* p) {
    uint32_t a;
    asm("{ .reg .u64 t; cvta.to.shared.u64 t, %1; cvt.u32.u64 %0, t; }" : "=r"(a) : "l"(p));
    return a;
}
__device__ __forceinline__ void ldsm4(uint32_t* r, uint32_t addr) {
    asm volatile("ldmatrix.sync.aligned.m8n8.x4.shared.b16 {%0,%1,%2,%3}, [%4];"
        : "=r"(r[0]), "=r"(r[1]), "=r"(r[2]), "=r"(r[3]) : "r"(addr));
}
__device__ __forceinline__ void mma_bf16(float* d, const uint32_t* a, const uint32_t* b) {
    asm volatile(
        "mma.sync.aligned.m16n8k16.row.col.f32.bf16.bf16.f32 "
        "{%0,%1,%2,%3}, {%4,%5,%6,%7}, {%8,%9}, {%0,%1,%2,%3};"
        : "+f"(d[0]), "+f"(d[1]), "+f"(d[2]), "+f"(d[3])
        : "r"(a[0]), "r"(a[1]), "r"(a[2]), "r"(a[3]), "r"(b[0]), "r"(b[1]));
}
__device__ __forceinline__ uint32_t bits2(__nv_bfloat162 v) { return *(uint32_t*)&v; }

// ---------------------------------------------------------------------------
// split fp32 -> bf16 hi + bf16 lo planes (x = hi + lo). n % 1024 == 0.
// ---------------------------------------------------------------------------
__global__ void __launch_bounds__(256) split_f32(
    const float* __restrict__ src, __nv_bfloat16* __restrict__ h,
    __nv_bfloat16* __restrict__ l, int n)
{
    int i = (blockIdx.x * 256 + threadIdx.x) * 4;
    if (i >= n) return;
    float4 v = *(const float4*)(src + i);
    __nv_bfloat162 h0 = __float22bfloat162_rn(make_float2(v.x, v.y));
    __nv_bfloat162 h1 = __float22bfloat162_rn(make_float2(v.z, v.w));
    float2 f0 = __bfloat1622float2(h0), f1 = __bfloat1622float2(h1);
    __nv_bfloat162 l0 = __float22bfloat162_rn(make_float2(v.x - f0.x, v.y - f0.y));
    __nv_bfloat162 l1 = __float22bfloat162_rn(make_float2(v.z - f1.x, v.w - f1.y));
    *(uint2*)(h + i) = make_uint2(bits2(h0), bits2(h1));
    *(uint2*)(l + i) = make_uint2(bits2(l0), bits2(l1));
}

// ---------------------------------------------------------------------------
// bf16x3 HMMA GEMM on pre-split hi/lo planes (R7 loop skeleton, no cp.async).
// C = (A @ W^T + bias) * alpha ; acc += Ah*Wh + Ah*Wl + Al*Wh.
// BM=128, BN=128, BK=16, 256 threads, 8 warps (2x4 -> 64x32 warp tiles).
// Register-staged double buffer, 48B-stride smem rows (R7-proven layout).
// mode 0: fp32 C=o1 (ldc). mode 1: split bf16 -> o1 hi plane, o2 lo plane.
// mode 2: fp32 dual -> o1 and o2 (row remap (m>>9)*513+(m&511)+1, ld D_).
// ---------------------------------------------------------------------------
#define AST     48                       // smem row stride (bytes)
#define PLANE   (128 * AST)              // 6144 B
#define STAGE   (4 * PLANE)              // 24576 B : Ah,Al,Wh,Wl
#define SMEM_TOTAL (2 * STAGE)           // 49152 B (static)

__global__ void __launch_bounds__(256, 2) gemm_mma(
    const __nv_bfloat16* __restrict__ Ah, const __nv_bfloat16* __restrict__ Al,
    const __nv_bfloat16* __restrict__ Wh, const __nv_bfloat16* __restrict__ Wl,
    const float* __restrict__ bias, int K, int ldc,
    const int* __restrict__ gather, float alpha, int mode,
    void* __restrict__ o1, void* __restrict__ o2)
{
    __shared__ __align__(128) char smem[SMEM_TOTAL];
    const uint32_t sb = smem_u32(smem);
    const int tid = threadIdx.x, wid = tid >> 5, lane = tid & 31;
    const int bm = blockIdx.y * 128, bn = blockIdx.x * 128;
    const int warp_m = wid >> 2, warp_n = wid & 3;

    // ---- writer mapping: row = tid>>1 (0..127), k-half = tid&1 -------------
    const int wrow = tid >> 1;
    const int wkh  = tid & 1;
    long arowIdx;
    {
        int m = bm + wrow;
        arowIdx = gather ? ((long)((m >> 9) * S_ + gather[m])) : (long)m;
    }
    const __nv_bfloat16* aH = Ah + arowIdx * K + wkh * 8;
    const __nv_bfloat16* aL = Al + arowIdx * K + wkh * 8;
    const __nv_bfloat16* wH = Wh + (long)(bn + wrow) * K + wkh * 8;
    const __nv_bfloat16* wL = Wl + (long)(bn + wrow) * K + wkh * 8;
    const uint32_t wst = (uint32_t)(wrow * AST + wkh * 16);

    // ---- ldmatrix lane addresses (within a stage; R7-proven) ---------------
    uint32_t a_addr[4];
    {
        int r  = (lane & 7) + ((lane >> 3) & 1) * 8;
        int kh = (lane >> 4) & 1;
        #pragma unroll
        for (int mt = 0; mt < 4; mt++)
            a_addr[mt] = (uint32_t)((warp_m * 64 + mt * 16 + r) * AST + kh * 16);
    }
    uint32_t b_addr[2];
    {
        int r  = (lane & 7) + ((lane >> 4) & 1) * 8;
        int kh = (lane >> 3) & 1;
        #pragma unroll
        for (int np = 0; np < 2; np++)
            b_addr[np] = (uint32_t)(2 * PLANE + (warp_n * 32 + np * 16 + r) * AST + kh * 16);
    }

    float acc[4][4][4];
    #pragma unroll
    for (int i = 0; i < 4; i++)
        #pragma unroll
        for (int j = 0; j < 4; j++)
            #pragma unroll
            for (int k = 0; k < 4; k++) acc[i][j][k] = 0.f;

    const int nch = K / 16;

    // ---- prologue: chunk 0 -> stage 0 --------------------------------------
    {
        uint4 vah = *(const uint4*)(aH);
        uint4 val = *(const uint4*)(aL);
        uint4 vwh = *(const uint4*)(wH);
        uint4 vwl = *(const uint4*)(wL);
        *(uint4*)(smem + wst)             = vah;
        *(uint4*)(smem + PLANE + wst)     = val;
        *(uint4*)(smem + 2 * PLANE + wst) = vwh;
        *(uint4*)(smem + 3 * PLANE + wst) = vwl;
    }
    __syncthreads();

    for (int c = 0; c < nch; c++) {
        // prefetch next chunk globals into registers
        uint4 pah, pal, pwh, pwl;
        if (c + 1 < nch) {
            pah = *(const uint4*)(aH + (c + 1) * 16);
            pal = *(const uint4*)(aL + (c + 1) * 16);
            pwh = *(const uint4*)(wH + (c + 1) * 16);
            pwl = *(const uint4*)(wL + (c + 1) * 16);
        }

        // compute from stage c&1
        const uint32_t st = sb + (c & 1) * STAGE;
        uint32_t bh[4][2], bl[4][2];
        #pragma unroll
        for (int np = 0; np < 2; np++) {
            uint32_t r[4];
            ldsm4(r, st + b_addr[np]);
            bh[2 * np][0] = r[0]; bh[2 * np][1] = r[1];
            bh[2 * np + 1][0] = r[2]; bh[2 * np + 1][1] = r[3];
            ldsm4(r, st + b_addr[np] + PLANE);
            bl[2 * np][0] = r[0]; bl[2 * np][1] = r[1];
            bl[2 * np + 1][0] = r[2]; bl[2 * np + 1][1] = r[3];
        }
        #pragma unroll
        for (int mt = 0; mt < 4; mt++) {
            uint32_t ahf[4], alf[4];
            ldsm4(ahf, st + a_addr[mt]);
            ldsm4(alf, st + a_addr[mt] + PLANE);
            #pragma unroll
            for (int nt = 0; nt < 4; nt++) {
                mma_bf16(acc[mt][nt], ahf, bh[nt]);
                mma_bf16(acc[mt][nt], ahf, bl[nt]);
                mma_bf16(acc[mt][nt], alf, bh[nt]);
            }
        }

        // store next chunk into the other stage
        if (c + 1 < nch) {
            char* stn = smem + ((c + 1) & 1) * STAGE;
            *(uint4*)(stn + wst)             = pah;
            *(uint4*)(stn + PLANE + wst)     = pal;
            *(uint4*)(stn + 2 * PLANE + wst) = pwh;
            *(uint4*)(stn + 3 * PLANE + wst) = pwl;
        }
        __syncthreads();
    }

    // ---- epilogue ----------------------------------------------------------
    const int mrow = (lane >> 2);
    const int ncol = 2 * (lane & 3);
    #pragma unroll
    for (int mt = 0; mt < 4; mt++) {
        #pragma unroll
        for (int nt = 0; nt < 4; nt++) {
            int m0 = bm + warp_m * 64 + mt * 16 + mrow;
            int n  = bn + warp_n * 32 + nt * 8 + ncol;
            float2 bb = *(const float2*)(bias + n);
            float2 r0, r1;
            r0.x = (acc[mt][nt][0] + bb.x) * alpha;
            r0.y = (acc[mt][nt][1] + bb.y) * alpha;
            r1.x = (acc[mt][nt][2] + bb.x) * alpha;
            r1.y = (acc[mt][nt][3] + bb.y) * alpha;
            if (mode == 0) {
                float* C = (float*)o1;
                *(float2*)(C + (long)m0 * ldc + n)       = r0;
                *(float2*)(C + (long)(m0 + 8) * ldc + n) = r1;
            } else if (mode == 1) {
                __nv_bfloat16* OH = (__nv_bfloat16*)o1;
                __nv_bfloat16* OL = (__nv_bfloat16*)o2;
                __nv_bfloat162 h0 = __float22bfloat162_rn(r0);
                __nv_bfloat162 h1 = __float22bfloat162_rn(r1);
                float2 f0 = __bfloat1622float2(h0), f1 = __bfloat1622float2(h1);
                __nv_bfloat162 l0 = __float22bfloat162_rn(make_float2(r0.x - f0.x, r0.y - f0.y));
                __nv_bfloat162 l1 = __float22bfloat162_rn(make_float2(r1.x - f1.x, r1.y - f1.y));
                *(uint32_t*)(OH + (long)m0 * ldc + n)       = bits2(h0);
                *(uint32_t*)(OH + (long)(m0 + 8) * ldc + n) = bits2(h1);
                *(uint32_t*)(OL + (long)m0 * ldc + n)       = bits2(l0);
                *(uint32_t*)(OL + (long)(m0 + 8) * ldc + n) = bits2(l1);
            } else {
                float* C  = (float*)o1;
                float* C2 = (float*)o2;
                *(float2*)(C + (long)m0 * ldc + n)       = r0;
                *(float2*)(C + (long)(m0 + 8) * ldc + n) = r1;
                long q0 = (long)((m0 >> 9) * (L_ + 1) + (m0 & (L_ - 1)) + 1);
                int  m1 = m0 + 8;
                long q1 = (long)((m1 >> 9) * (L_ + 1) + (m1 & (L_ - 1)) + 1);
                *(float2*)(C2 + q0 * D_ + n) = r0;
                *(float2*)(C2 + q1 * D_ + n) = r1;
            }
        }
    }
}

// ---------------------------------------------------------------------------
// Index conversion with dtype sniffing (int32 or int64 LE).
// ---------------------------------------------------------------------------
__global__ void __launch_bounds__(256) conv_idx_kernel(
    const unsigned int* __restrict__ src, int n, int* __restrict__ dst)
{
    __shared__ unsigned s_or[8];
    __shared__ int s_is64;
    const int tid = threadIdx.x;
    unsigned acc = 0;
    for (int i = tid; 2 * i + 1 < n; i += 256) acc |= src[2 * i + 1];
    #pragma unroll
    for (int off = 16; off > 0; off >>= 1)
        acc |= __shfl_xor_sync(0xFFFFFFFFu, acc, off);
    if ((tid & 31) == 0) s_or[tid >> 5] = acc;
    __syncthreads();
    if (tid == 0) {
        unsigned t = 0;
        #pragma unroll
        for (int i = 0; i < 8; i++) t |= s_or[i];
        s_is64 = (t == 0u);
    }
    __syncthreads();
    const int is64 = s_is64;
    for (int i = tid; i < n; i += 256)
        dst[i] = (int)(is64 ? src[2 * i] : src[i]);
}

// ---------------------------------------------------------------------------
// Sparse masked attention. Writes ctx as bf16 hi/lo planes.
// ---------------------------------------------------------------------------
__global__ void __launch_bounds__(256) attn_kernel(
    const float* __restrict__ Q, const float* __restrict__ Kb,
    const float* __restrict__ Vb,
    const int* __restrict__ sem_syn, const int* __restrict__ to_sem,
    __nv_bfloat16* __restrict__ CtxH, __nv_bfloat16* __restrict__ CtxL)
{
    const int bl = blockIdx.x;
    const int b  = bl >> 9;
    const int l  = bl & (L_ - 1);

    __shared__ int   s_list[MAXN];
    __shared__ int   s_n;
    __shared__ float s_scores[H_][MAXN];

    const int tid  = threadIdx.x;
    const int w    = tid >> 5;
    const int lane = tid & 31;

    if (w == 0) {
        int cnt = 0;
        const int* syn = sem_syn + b * S_;
        #pragma unroll 4
        for (int c = 0; c < S_ / 32; c++) {
            int s = c * 32 + lane;
            int ok = (syn[s] == l + 1);
            unsigned msk = __ballot_sync(0xFFFFFFFFu, ok);
            if (ok) {
                int pos = cnt + __popc(msk & ((1u << lane) - 1));
                if (pos < MAXN) s_list[pos] = s;
            }
            cnt += __popc(msk);
        }
        if (lane == 0) {
            int sp = to_sem[bl];
            if (syn[sp] != l + 1) {
                if (cnt < MAXN) s_list[cnt] = sp;
                cnt++;
            }
            s_n = (cnt < MAXN) ? cnt : MAXN;
        }
    }
    __syncthreads();
    const int n = s_n;

    const long hoff = (long)w * DH_ + lane * 4;
    float4 q = *(const float4*)(Q + (long)bl * D_ + hoff);

    for (int i = 0; i < n; i++) {
        int s = s_list[i];
        float4 k4 = *(const float4*)(Kb + ((long)(b * S_ + s)) * D_ + hoff);
        float d = q.x * k4.x + q.y * k4.y + q.z * k4.z + q.w * k4.w;
        #pragma unroll
        for (int off = 16; off > 0; off >>= 1)
            d += __shfl_xor_sync(0xFFFFFFFFu, d, off);
        if (lane == 0) s_scores[w][i] = d;
    }
    __syncwarp();

    float mx = -1e30f;
    for (int i = 0; i < n; i++) mx = fmaxf(mx, s_scores[w][i]);
    float sum = 0.f;
    for (int i = 0; i < n; i++) sum += expf(s_scores[w][i] - mx);
    float inv = 1.f / sum;

    float4 acc = make_float4(0.f, 0.f, 0.f, 0.f);
    for (int i = 0; i < n; i++) {
        float p = expf(s_scores[w][i] - mx) * inv;
        float4 v4 = *(const float4*)(Vb + ((long)(b * S_ + s_list[i])) * D_ + hoff);
        acc.x += p * v4.x; acc.y += p * v4.y;
        acc.z += p * v4.z; acc.w += p * v4.w;
    }
    __nv_bfloat162 h0 = __float22bfloat162_rn(make_float2(acc.x, acc.y));
    __nv_bfloat162 h1 = __float22bfloat162_rn(make_float2(acc.z, acc.w));
    float2 f0 = __bfloat1622float2(h0), f1 = __bfloat1622float2(h1);
    __nv_bfloat162 l0 = __float22bfloat162_rn(make_float2(acc.x - f0.x, acc.y - f0.y));
    __nv_bfloat162 l1 = __float22bfloat162_rn(make_float2(acc.z - f1.x, acc.w - f1.y));
    *(uint2*)(CtxH + (long)bl * D_ + hoff) = make_uint2(bits2(h0), bits2(h1));
    *(uint2*)(CtxL + (long)bl * D_ + hoff) = make_uint2(bits2(l0), bits2(l1));
}

// type_vec: concat[:, 1024:1280] = type_emb[to_sem_type], split hi/lo
__global__ void type_copy_kernel(const int* __restrict__ to_sem_type,
                                 const float* __restrict__ type_emb,
                                 __nv_bfloat16* __restrict__ catH,
                                 __nv_bfloat16* __restrict__ catL)
{
    int m = blockIdx.x;
    int j = threadIdx.x;
    float v = type_emb[(long)to_sem_type[m] * WD_ + j];
    __nv_bfloat16 h = __float2bfloat16_rn(v);
    __nv_bfloat16 l = __float2bfloat16_rn(v - __bfloat162float(h));
    catH[(long)m * CK_ + D_ + j] = h;
    catL[(long)m * CK_ + D_ + j] = l;
}

// out2[b, 0, :] = bias_root
__global__ void root_fill_kernel(const float* __restrict__ bias_root,
                                 float* __restrict__ out2)
{
    int idx = blockIdx.x * 256 + threadIdx.x;
    int b = idx >> 10, d = idx & (D_ - 1);
    out2[(long)b * (L_ + 1) * D_ + d] = bias_root[d];
}

// ---------------------------------------------------------------------------
extern "C" void kernel_launch(void* const* d_in, const int* in_sizes, int n_in,
                              void* d_out, int out_size)
{
    const float* enc        = (const float*)d_in[0];
    const void*  to_sem_raw = d_in[1];
    const void*  typ_raw    = d_in[2];
    const void*  syn_raw    = d_in[3];
    const float* wq = (const float*)d_in[4];  const float* bq = (const float*)d_in[5];
    const float* wk = (const float*)d_in[6];  const float* bk = (const float*)d_in[7];
    const float* wv = (const float*)d_in[8];  const float* bv = (const float*)d_in[9];
    const float* wo = (const float*)d_in[10]; const float* bo = (const float*)d_in[11];
    const float* type_emb  = (const float*)d_in[12];
    const float* w_proj    = (const float*)d_in[13];
    const float* b_proj    = (const float*)d_in[14];
    const float* bias_root = (const float*)d_in[15];

    float* out1 = (float*)d_out;
    float* out2 = out1 + (long)B_ * L_ * D_;

    float *pK, *pV, *pQ;
    __nv_bfloat16 *pEncH, *pEncL, *pWkH, *pWkL, *pWvH, *pWvL, *pWqH, *pWqL;
    __nv_bfloat16 *pWoH, *pWoL, *pWpH, *pWpL, *pCtxH, *pCtxL, *pCatH, *pCatL;
    int *pToSem, *pToSemType, *pSemSyn;
    cudaGetSymbolAddress((void**)&pK, gK);
    cudaGetSymbolAddress((void**)&pV, gV);
    cudaGetSymbolAddress((void**)&pQ, gQ);
    cudaGetSymbolAddress((void**)&pEncH, gEncH); cudaGetSymbolAddress((void**)&pEncL, gEncL);
    cudaGetSymbolAddress((void**)&pWkH, gWkH);   cudaGetSymbolAddress((void**)&pWkL, gWkL);
    cudaGetSymbolAddress((void**)&pWvH, gWvH);   cudaGetSymbolAddress((void**)&pWvL, gWvL);
    cudaGetSymbolAddress((void**)&pWqH, gWqH);   cudaGetSymbolAddress((void**)&pWqL, gWqL);
    cudaGetSymbolAddress((void**)&pWoH, gWoH);   cudaGetSymbolAddress((void**)&pWoL, gWoL);
    cudaGetSymbolAddress((void**)&pWpH, gWpH);   cudaGetSymbolAddress((void**)&pWpL, gWpL);
    cudaGetSymbolAddress((void**)&pCtxH, gCtxH); cudaGetSymbolAddress((void**)&pCtxL, gCtxL);
    cudaGetSymbolAddress((void**)&pCatH, gCatH); cudaGetSymbolAddress((void**)&pCatL, gCatL);
    cudaGetSymbolAddress((void**)&pToSem, gToSem);
    cudaGetSymbolAddress((void**)&pToSemType, gToSemType);
    cudaGetSymbolAddress((void**)&pSemSyn, gSemSyn);

    const float qscale = 0.08838834764831845f;   // DH^-0.5
    dim3 blk(256);

    conv_idx_kernel<<<1, blk>>>((const unsigned int*)to_sem_raw, B_ * L_, pToSem);
    conv_idx_kernel<<<1, blk>>>((const unsigned int*)typ_raw,    B_ * L_, pToSemType);
    conv_idx_kernel<<<1, blk>>>((const unsigned int*)syn_raw,    B_ * S_, pSemSyn);

    // one-time fp32 -> bf16 hi/lo splits
    split_f32<<<(B_ * S_ * D_) / 1024, blk>>>(enc, pEncH, pEncL, B_ * S_ * D_);
    split_f32<<<(D_ * D_) / 1024, blk>>>(wk, pWkH, pWkL, D_ * D_);
    split_f32<<<(D_ * D_) / 1024, blk>>>(wv, pWvH, pWvL, D_ * D_);
    split_f32<<<(D_ * D_) / 1024, blk>>>(wq, pWqH, pWqL, D_ * D_);
    split_f32<<<(D_ * D_) / 1024, blk>>>(wo, pWoH, pWoL, D_ * D_);
    split_f32<<<(D_ * CK_) / 1024, blk>>>(w_proj, pWpH, pWpL, D_ * CK_);

    // K/V projections -> fp32
    gemm_mma<<<dim3(D_ / 128, (B_ * S_) / 128), blk>>>(
        pEncH, pEncL, pWkH, pWkL, bk, D_, D_, nullptr, 1.f, 0, pK, nullptr);
    gemm_mma<<<dim3(D_ / 128, (B_ * S_) / 128), blk>>>(
        pEncH, pEncL, pWvH, pWvL, bv, D_, D_, nullptr, 1.f, 0, pV, nullptr);

    // Q projection with fused gather + scale -> fp32
    gemm_mma<<<dim3(D_ / 128, (B_ * L_) / 128), blk>>>(
        pEncH, pEncL, pWqH, pWqL, bq, D_, D_, pToSem, qscale, 0, pQ, nullptr);

    // sparse attention -> ctx hi/lo
    attn_kernel<<<B_ * L_, blk>>>(pQ, pK, pV, pSemSyn, pToSem, pCtxH, pCtxL);

    // O projection -> concat hi/lo planes, cols [0,1024), ldc=1280
    gemm_mma<<<dim3(D_ / 128, (B_ * L_) / 128), blk>>>(
        pCtxH, pCtxL, pWoH, pWoL, bo, D_, CK_, nullptr, 1.f, 1, pCatH, pCatL);

    // type embedding -> concat hi/lo cols [1024,1280)
    type_copy_kernel<<<B_ * L_, blk>>>(pToSemType, type_emb, pCatH, pCatL);

    // final projection K=1280 -> both fp32 outputs
    gemm_mma<<<dim3(D_ / 128, (B_ * L_) / 128), blk>>>(
        pCatH, pCatL, pWpH, pWpL, b_proj, CK_, D_, nullptr, 1.f, 2, out1, out2);

    root_fill_kernel<<<(B_ * D_) / 256, blk>>>(bias_root, out2);
}

// round 11
// speedup vs baseline: 2.4362x; 1.0412x over previous
#include <cuda_runtime.h>
#include <cuda_bf16.h>
#include <math.h>
#include <stdint.h>

// Problem constants
#define B_  16
#define S_  1024
#define L_  512
#define D_  1024
#define H_  8
#define DH_ 128
#define WD_ 256
#define CK_ (D_ + WD_)     // 1280
#define MAXN 128

// ---------------- scratch ----------------------------------------------------
__device__ __align__(256) float gK[B_ * S_ * D_];
__device__ __align__(256) float gQ[B_ * L_ * D_];
__device__ __align__(256) float gFT[1024 * D_];            // fused type table (fp32)
__device__ __align__(256) __nv_bfloat16 gEncH[B_ * S_ * D_];
__device__ __align__(256) __nv_bfloat16 gEncL[B_ * S_ * D_];
__device__ __align__(256) __nv_bfloat16 gWkH[D_ * D_];
__device__ __align__(256) __nv_bfloat16 gWkL[D_ * D_];
__device__ __align__(256) __nv_bfloat16 gWvH[D_ * D_];
__device__ __align__(256) __nv_bfloat16 gWvL[D_ * D_];
__device__ __align__(256) __nv_bfloat16 gWqH[D_ * D_];
__device__ __align__(256) __nv_bfloat16 gWqL[D_ * D_];
__device__ __align__(256) __nv_bfloat16 gWoH[D_ * D_];
__device__ __align__(256) __nv_bfloat16 gWoL[D_ * D_];
__device__ __align__(256) __nv_bfloat16 gWpH[D_ * CK_];
__device__ __align__(256) __nv_bfloat16 gWpL[D_ * CK_];
__device__ __align__(256) __nv_bfloat16 gTeH[1024 * WD_];  // type_emb split (padded rows zero)
__device__ __align__(256) __nv_bfloat16 gTeL[1024 * WD_];
__device__ __align__(256) __nv_bfloat16 gZH[H_ * B_ * L_ * D_];   // Z = P@enc, per head
__device__ __align__(256) __nv_bfloat16 gZL[H_ * B_ * L_ * D_];
__device__ __align__(256) __nv_bfloat16 gCtxH[B_ * L_ * D_];
__device__ __align__(256) __nv_bfloat16 gCtxL[B_ * L_ * D_];
__device__ __align__(256) __nv_bfloat16 gOutH[B_ * L_ * D_];      // O-proj output
__device__ __align__(256) __nv_bfloat16 gOutL[B_ * L_ * D_];
__device__ float gZeroB[D_];                                      // zero bias (static init 0)
__device__ int gToSem[B_ * L_];
__device__ int gToSemType[B_ * L_];
__device__ int gSemSyn[B_ * S_];

// ---------------- helpers ----------------------------------------------------
__device__ __forceinline__ uint32_t smem_u32(const void* p) {
    uint32_t a;
    asm("{ .reg .u64 t; cvta.to.shared.u64 t, %1; cvt.u32.u64 %0, t; }" : "=r"(a) : "l"(p));
    return a;
}
__device__ __forceinline__ void ldsm4(uint32_t* r, uint32_t addr) {
    asm volatile("ldmatrix.sync.aligned.m8n8.x4.shared.b16 {%0,%1,%2,%3}, [%4];"
        : "=r"(r[0]), "=r"(r[1]), "=r"(r[2]), "=r"(r[3]) : "r"(addr));
}
__device__ __forceinline__ void mma_bf16(float* d, const uint32_t* a, const uint32_t* b) {
    asm volatile(
        "mma.sync.aligned.m16n8k16.row.col.f32.bf16.bf16.f32 "
        "{%0,%1,%2,%3}, {%4,%5,%6,%7}, {%8,%9}, {%0,%1,%2,%3};"
        : "+f"(d[0]), "+f"(d[1]), "+f"(d[2]), "+f"(d[3])
        : "r"(a[0]), "r"(a[1]), "r"(a[2]), "r"(a[3]), "r"(b[0]), "r"(b[1]));
}
__device__ __forceinline__ uint32_t bits2(__nv_bfloat162 v) { return *(uint32_t*)&v; }

// ---------------------------------------------------------------------------
// split fp32 -> bf16 hi + bf16 lo planes (x = hi + lo).
// ---------------------------------------------------------------------------
__global__ void __launch_bounds__(256) split_f32(
    const float* __restrict__ src, __nv_bfloat16* __restrict__ h,
    __nv_bfloat16* __restrict__ l, int n)
{
    int i = (blockIdx.x * 256 + threadIdx.x) * 4;
    if (i >= n) return;
    float4 v = *(const float4*)(src + i);
    __nv_bfloat162 h0 = __float22bfloat162_rn(make_float2(v.x, v.y));
    __nv_bfloat162 h1 = __float22bfloat162_rn(make_float2(v.z, v.w));
    float2 f0 = __bfloat1622float2(h0), f1 = __bfloat1622float2(h1);
    __nv_bfloat162 l0 = __float22bfloat162_rn(make_float2(v.x - f0.x, v.y - f0.y));
    __nv_bfloat162 l1 = __float22bfloat162_rn(make_float2(v.z - f1.x, v.w - f1.y));
    *(uint2*)(h + i) = make_uint2(bits2(h0), bits2(h1));
    *(uint2*)(l + i) = make_uint2(bits2(l0), bits2(l1));
}

// ---------------------------------------------------------------------------
// bf16x3 HMMA GEMM on pre-split hi/lo planes (R10-proven mainloop).
// C = (A @ W^T + bias) * alpha ; acc += Ah*Wh + Ah*Wl + Al*Wh.
// BM=128, BN=128, BK=16, 256 threads, 8 warps (2x4 -> 64x32 warp tiles).
// A row stride == K. W row stride == ldw (>= K).
// blockIdx.z offsets: A += z*aZ, W += z*wZ, bias += z*bZ, out cols += z*cZ.
// mode 0: fp32 C=o1 (ldc). mode 1: split bf16 -> o1 hi plane, o2 lo plane.
// mode 2: fp32 dual -> o1 and o2 (row remap (m>>9)*513+(m&511)+1, ld D_).
// ---------------------------------------------------------------------------
#define AST     48                       // smem row stride (bytes)
#define PLANE   (128 * AST)              // 6144 B
#define STAGE   (4 * PLANE)              // 24576 B : Ah,Al,Wh,Wl
#define SMEM_TOTAL (2 * STAGE)           // 49152 B (static)

__global__ void __launch_bounds__(256, 2) gemm_mma(
    const __nv_bfloat16* __restrict__ Ah, const __nv_bfloat16* __restrict__ Al,
    const __nv_bfloat16* __restrict__ Wh, const __nv_bfloat16* __restrict__ Wl,
    const float* __restrict__ bias, int K, int ldw, int ldc,
    const int* __restrict__ gather, float alpha, int mode,
    void* __restrict__ o1, void* __restrict__ o2,
    long aZ, long wZ, int bZ, int cZ)
{
    __shared__ __align__(128) char smem[SMEM_TOTAL];
    const uint32_t sb = smem_u32(smem);
    const int tid = threadIdx.x, wid = tid >> 5, lane = tid & 31;
    const int bm = blockIdx.y * 128, bn = blockIdx.x * 128;
    const int warp_m = wid >> 2, warp_n = wid & 3;

    const int zz = blockIdx.z;
    Ah += (long)zz * aZ;  Al += (long)zz * aZ;
    Wh += (long)zz * wZ;  Wl += (long)zz * wZ;
    bias += (long)zz * bZ;
    const long oOff = (long)zz * cZ;     // output column element offset

    // ---- writer mapping: row = tid>>1 (0..127), k-half = tid&1 -------------
    const int wrow = tid >> 1;
    const int wkh  = tid & 1;
    long arowIdx;
    {
        int m = bm + wrow;
        arowIdx = gather ? ((long)((m >> 9) * S_ + gather[m])) : (long)m;
    }
    const __nv_bfloat16* aH = Ah + arowIdx * K + wkh * 8;
    const __nv_bfloat16* aL = Al + arowIdx * K + wkh * 8;
    const __nv_bfloat16* wH = Wh + (long)(bn + wrow) * ldw + wkh * 8;
    const __nv_bfloat16* wL = Wl + (long)(bn + wrow) * ldw + wkh * 8;
    const uint32_t wst = (uint32_t)(wrow * AST + wkh * 16);

    // ---- ldmatrix lane addresses (within a stage) --------------------------
    uint32_t a_addr[4];
    {
        int r  = (lane & 7) + ((lane >> 3) & 1) * 8;
        int kh = (lane >> 4) & 1;
        #pragma unroll
        for (int mt = 0; mt < 4; mt++)
            a_addr[mt] = (uint32_t)((warp_m * 64 + mt * 16 + r) * AST + kh * 16);
    }
    uint32_t b_addr[2];
    {
        int r  = (lane & 7) + ((lane >> 4) & 1) * 8;
        int kh = (lane >> 3) & 1;
        #pragma unroll
        for (int np = 0; np < 2; np++)
            b_addr[np] = (uint32_t)(2 * PLANE + (warp_n * 32 + np * 16 + r) * AST + kh * 16);
    }

    float acc[4][4][4];
    #pragma unroll
    for (int i = 0; i < 4; i++)
        #pragma unroll
        for (int j = 0; j < 4; j++)
            #pragma unroll
            for (int k = 0; k < 4; k++) acc[i][j][k] = 0.f;

    const int nch = K / 16;

    // ---- prologue: chunk 0 -> stage 0 --------------------------------------
    {
        uint4 vah = *(const uint4*)(aH);
        uint4 val = *(const uint4*)(aL);
        uint4 vwh = *(const uint4*)(wH);
        uint4 vwl = *(const uint4*)(wL);
        *(uint4*)(smem + wst)             = vah;
        *(uint4*)(smem + PLANE + wst)     = val;
        *(uint4*)(smem + 2 * PLANE + wst) = vwh;
        *(uint4*)(smem + 3 * PLANE + wst) = vwl;
    }
    __syncthreads();

    for (int c = 0; c < nch; c++) {
        uint4 pah, pal, pwh, pwl;
        if (c + 1 < nch) {
            pah = *(const uint4*)(aH + (c + 1) * 16);
            pal = *(const uint4*)(aL + (c + 1) * 16);
            pwh = *(const uint4*)(wH + (c + 1) * 16);
            pwl = *(const uint4*)(wL + (c + 1) * 16);
        }

        const uint32_t st = sb + (c & 1) * STAGE;
        uint32_t bh[4][2], bl[4][2];
        #pragma unroll
        for (int np = 0; np < 2; np++) {
            uint32_t r[4];
            ldsm4(r, st + b_addr[np]);
            bh[2 * np][0] = r[0]; bh[2 * np][1] = r[1];
            bh[2 * np + 1][0] = r[2]; bh[2 * np + 1][1] = r[3];
            ldsm4(r, st + b_addr[np] + PLANE);
            bl[2 * np][0] = r[0]; bl[2 * np][1] = r[1];
            bl[2 * np + 1][0] = r[2]; bl[2 * np + 1][1] = r[3];
        }
        #pragma unroll
        for (int mt = 0; mt < 4; mt++) {
            uint32_t ahf[4], alf[4];
            ldsm4(ahf, st + a_addr[mt]);
            ldsm4(alf, st + a_addr[mt] + PLANE);
            #pragma unroll
            for (int nt = 0; nt < 4; nt++) {
                mma_bf16(acc[mt][nt], ahf, bh[nt]);
                mma_bf16(acc[mt][nt], ahf, bl[nt]);
                mma_bf16(acc[mt][nt], alf, bh[nt]);
            }
        }

        if (c + 1 < nch) {
            char* stn = smem + ((c + 1) & 1) * STAGE;
            *(uint4*)(stn + wst)             = pah;
            *(uint4*)(stn + PLANE + wst)     = pal;
            *(uint4*)(stn + 2 * PLANE + wst) = pwh;
            *(uint4*)(stn + 3 * PLANE + wst) = pwl;
        }
        __syncthreads();
    }

    // ---- epilogue ----------------------------------------------------------
    const int mrow = (lane >> 2);
    const int ncol = 2 * (lane & 3);
    #pragma unroll
    for (int mt = 0; mt < 4; mt++) {
        #pragma unroll
        for (int nt = 0; nt < 4; nt++) {
            int m0 = bm + warp_m * 64 + mt * 16 + mrow;
            int n  = bn + warp_n * 32 + nt * 8 + ncol;
            float2 bb = *(const float2*)(bias + n);
            float2 r0, r1;
            r0.x = (acc[mt][nt][0] + bb.x) * alpha;
            r0.y = (acc[mt][nt][1] + bb.y) * alpha;
            r1.x = (acc[mt][nt][2] + bb.x) * alpha;
            r1.y = (acc[mt][nt][3] + bb.y) * alpha;
            if (mode == 0) {
                float* C = (float*)o1;
                *(float2*)(C + (long)m0 * ldc + n + oOff)       = r0;
                *(float2*)(C + (long)(m0 + 8) * ldc + n + oOff) = r1;
            } else if (mode == 1) {
                __nv_bfloat16* OH = (__nv_bfloat16*)o1;
                __nv_bfloat16* OL = (__nv_bfloat16*)o2;
                __nv_bfloat162 h0 = __float22bfloat162_rn(r0);
                __nv_bfloat162 h1 = __float22bfloat162_rn(r1);
                float2 f0 = __bfloat1622float2(h0), f1 = __bfloat1622float2(h1);
                __nv_bfloat162 l0 = __float22bfloat162_rn(make_float2(r0.x - f0.x, r0.y - f0.y));
                __nv_bfloat162 l1 = __float22bfloat162_rn(make_float2(r1.x - f1.x, r1.y - f1.y));
                *(uint32_t*)(OH + (long)m0 * ldc + n + oOff)       = bits2(h0);
                *(uint32_t*)(OH + (long)(m0 + 8) * ldc + n + oOff) = bits2(h1);
                *(uint32_t*)(OL + (long)m0 * ldc + n + oOff)       = bits2(l0);
                *(uint32_t*)(OL + (long)(m0 + 8) * ldc + n + oOff) = bits2(l1);
            } else {
                float* C  = (float*)o1;
                float* C2 = (float*)o2;
                *(float2*)(C + (long)m0 * ldc + n)       = r0;
                *(float2*)(C + (long)(m0 + 8) * ldc + n) = r1;
                long q0 = (long)((m0 >> 9) * (L_ + 1) + (m0 & (L_ - 1)) + 1);
                int  m1 = m0 + 8;
                long q1 = (long)((m1 >> 9) * (L_ + 1) + (m1 & (L_ - 1)) + 1);
                *(float2*)(C2 + q0 * D_ + n) = r0;
                *(float2*)(C2 + q1 * D_ + n) = r1;
            }
        }
    }
}

// ---------------------------------------------------------------------------
// Index conversion with dtype sniffing (int32 or int64 LE).
// ---------------------------------------------------------------------------
__global__ void __launch_bounds__(256) conv_idx_kernel(
    const unsigned int* __restrict__ src, int n, int* __restrict__ dst)
{
    __shared__ unsigned s_or[8];
    __shared__ int s_is64;
    const int tid = threadIdx.x;
    unsigned acc = 0;
    for (int i = tid; 2 * i + 1 < n; i += 256) acc |= src[2 * i + 1];
    #pragma unroll
    for (int off = 16; off > 0; off >>= 1)
        acc |= __shfl_xor_sync(0xFFFFFFFFu, acc, off);
    if ((tid & 31) == 0) s_or[tid >> 5] = acc;
    __syncthreads();
    if (tid == 0) {
        unsigned t = 0;
        #pragma unroll
        for (int i = 0; i < 8; i++) t |= s_or[i];
        s_is64 = (t == 0u);
    }
    __syncthreads();
    const int is64 = s_is64;
    for (int i = tid; i < n; i += 256)
        dst[i] = (int)(is64 ? src[2 * i] : src[i]);
}

// ---------------------------------------------------------------------------
// Sparse masked attention. Scores from Q,K; then Z_h = sum_s p_s * enc[s]
// written as bf16 hi/lo planes (the V GEMM is applied to Z afterwards).
// ---------------------------------------------------------------------------
__global__ void __launch_bounds__(256) attn_kernel(
    const float* __restrict__ Q, const float* __restrict__ Kb,
    const float* __restrict__ enc,
    const int* __restrict__ sem_syn, const int* __restrict__ to_sem,
    __nv_bfloat16* __restrict__ ZH, __nv_bfloat16* __restrict__ ZL)
{
    const int bl = blockIdx.x;
    const int b  = bl >> 9;
    const int l  = bl & (L_ - 1);

    __shared__ int   s_list[MAXN];
    __shared__ int   s_n;
    __shared__ float s_scores[H_][MAXN];

    const int tid  = threadIdx.x;
    const int w    = tid >> 5;
    const int lane = tid & 31;

    if (w == 0) {
        int cnt = 0;
        const int* syn = sem_syn + b * S_;
        #pragma unroll 4
        for (int c = 0; c < S_ / 32; c++) {
            int s = c * 32 + lane;
            int ok = (syn[s] == l + 1);
            unsigned msk = __ballot_sync(0xFFFFFFFFu, ok);
            if (ok) {
                int pos = cnt + __popc(msk & ((1u << lane) - 1));
                if (pos < MAXN) s_list[pos] = s;
            }
            cnt += __popc(msk);
        }
        if (lane == 0) {
            int sp = to_sem[bl];
            if (syn[sp] != l + 1) {
                if (cnt < MAXN) s_list[cnt] = sp;
                cnt++;
            }
            s_n = (cnt < MAXN) ? cnt : MAXN;
        }
    }
    __syncthreads();
    const int n = s_n;

    const long hoff = (long)w * DH_ + lane * 4;
    float4 q = *(const float4*)(Q + (long)bl * D_ + hoff);

    for (int i = 0; i < n; i++) {
        int s = s_list[i];
        float4 k4 = *(const float4*)(Kb + ((long)(b * S_ + s)) * D_ + hoff);
        float d = q.x * k4.x + q.y * k4.y + q.z * k4.z + q.w * k4.w;
        #pragma unroll
        for (int off = 16; off > 0; off >>= 1)
            d += __shfl_xor_sync(0xFFFFFFFFu, d, off);
        if (lane == 0) s_scores[w][i] = d;
    }
    __syncwarp();

    float mx = -1e30f;
    for (int i = 0; i < n; i++) mx = fmaxf(mx, s_scores[w][i]);
    float sum = 0.f;
    for (int i = 0; i < n; i++) sum += expf(s_scores[w][i] - mx);
    float inv = 1.f / sum;

    // Z accumulation: each lane owns dims {j*128 + lane*4 .. +3}, j=0..7
    float4 za[8];
    #pragma unroll
    for (int j = 0; j < 8; j++) za[j] = make_float4(0.f, 0.f, 0.f, 0.f);
    for (int i = 0; i < n; i++) {
        float p = expf(s_scores[w][i] - mx) * inv;
        const float* er = enc + ((long)(b * S_ + s_list[i])) * D_;
        #pragma unroll
        for (int j = 0; j < 8; j++) {
            float4 e = *(const float4*)(er + j * 128 + lane * 4);
            za[j].x += p * e.x; za[j].y += p * e.y;
            za[j].z += p * e.z; za[j].w += p * e.w;
        }
    }
    const long zbase = (long)w * (B_ * L_ * (long)D_) + (long)bl * D_;
    #pragma unroll
    for (int j = 0; j < 8; j++) {
        float4 v = za[j];
        __nv_bfloat162 h0 = __float22bfloat162_rn(make_float2(v.x, v.y));
        __nv_bfloat162 h1 = __float22bfloat162_rn(make_float2(v.z, v.w));
        float2 f0 = __bfloat1622float2(h0), f1 = __bfloat1622float2(h1);
        __nv_bfloat162 l0 = __float22bfloat162_rn(make_float2(v.x - f0.x, v.y - f0.y));
        __nv_bfloat162 l1 = __float22bfloat162_rn(make_float2(v.z - f1.x, v.w - f1.y));
        long off = zbase + j * 128 + lane * 4;
        *(uint2*)(ZH + off) = make_uint2(bits2(h0), bits2(h1));
        *(uint2*)(ZL + off) = make_uint2(bits2(l0), bits2(l1));
    }
}

// out += FT[type[m]] for both outputs
__global__ void add_table_kernel(const int* __restrict__ to_sem_type,
                                 const float* __restrict__ FT,
                                 float* __restrict__ out1, float* __restrict__ out2)
{
    int m = blockIdx.x;
    int j = threadIdx.x * 4;
    float4 f = *(const float4*)(FT + (long)to_sem_type[m] * D_ + j);
    float4* p1 = (float4*)(out1 + (long)m * D_ + j);
    float4 v = *p1;
    v.x += f.x; v.y += f.y; v.z += f.z; v.w += f.w;
    *p1 = v;
    long r2 = (long)((m >> 9) * (L_ + 1) + (m & (L_ - 1)) + 1);
    *(float4*)(out2 + r2 * D_ + j) = v;
}

// out2[b, 0, :] = bias_root
__global__ void root_fill_kernel(const float* __restrict__ bias_root,
                                 float* __restrict__ out2)
{
    int idx = blockIdx.x * 256 + threadIdx.x;
    int b = idx >> 10, d = idx & (D_ - 1);
    out2[(long)b * (L_ + 1) * D_ + d] = bias_root[d];
}

// ---------------------------------------------------------------------------
extern "C" void kernel_launch(void* const* d_in, const int* in_sizes, int n_in,
                              void* d_out, int out_size)
{
    const float* enc        = (const float*)d_in[0];
    const void*  to_sem_raw = d_in[1];
    const void*  typ_raw    = d_in[2];
    const void*  syn_raw    = d_in[3];
    const float* wq = (const float*)d_in[4];  const float* bq = (const float*)d_in[5];
    const float* wk = (const float*)d_in[6];  const float* bk = (const float*)d_in[7];
    const float* wv = (const float*)d_in[8];  const float* bv = (const float*)d_in[9];
    const float* wo = (const float*)d_in[10]; const float* bo = (const float*)d_in[11];
    const float* type_emb  = (const float*)d_in[12];
    const float* w_proj    = (const float*)d_in[13];
    const float* b_proj    = (const float*)d_in[14];
    const float* bias_root = (const float*)d_in[15];

    float* out1 = (float*)d_out;
    float* out2 = out1 + (long)B_ * L_ * D_;

    float *pK, *pQ, *pFT, *pZeroB;
    __nv_bfloat16 *pEncH, *pEncL, *pWkH, *pWkL, *pWvH, *pWvL, *pWqH, *pWqL;
    __nv_bfloat16 *pWoH, *pWoL, *pWpH, *pWpL, *pTeH, *pTeL;
    __nv_bfloat16 *pZH, *pZL, *pCtxH, *pCtxL, *pOutH, *pOutL;
    int *pToSem, *pToSemType, *pSemSyn;
    cudaGetSymbolAddress((void**)&pK, gK);
    cudaGetSymbolAddress((void**)&pQ, gQ);
    cudaGetSymbolAddress((void**)&pFT, gFT);
    cudaGetSymbolAddress((void**)&pZeroB, gZeroB);
    cudaGetSymbolAddress((void**)&pEncH, gEncH); cudaGetSymbolAddress((void**)&pEncL, gEncL);
    cudaGetSymbolAddress((void**)&pWkH, gWkH);   cudaGetSymbolAddress((void**)&pWkL, gWkL);
    cudaGetSymbolAddress((void**)&pWvH, gWvH);   cudaGetSymbolAddress((void**)&pWvL, gWvL);
    cudaGetSymbolAddress((void**)&pWqH, gWqH);   cudaGetSymbolAddress((void**)&pWqL, gWqL);
    cudaGetSymbolAddress((void**)&pWoH, gWoH);   cudaGetSymbolAddress((void**)&pWoL, gWoL);
    cudaGetSymbolAddress((void**)&pWpH, gWpH);   cudaGetSymbolAddress((void**)&pWpL, gWpL);
    cudaGetSymbolAddress((void**)&pTeH, gTeH);   cudaGetSymbolAddress((void**)&pTeL, gTeL);
    cudaGetSymbolAddress((void**)&pZH, gZH);     cudaGetSymbolAddress((void**)&pZL, gZL);
    cudaGetSymbolAddress((void**)&pCtxH, gCtxH); cudaGetSymbolAddress((void**)&pCtxL, gCtxL);
    cudaGetSymbolAddress((void**)&pOutH, gOutH); cudaGetSymbolAddress((void**)&pOutL, gOutL);
    cudaGetSymbolAddress((void**)&pToSem, gToSem);
    cudaGetSymbolAddress((void**)&pToSemType, gToSemType);
    cudaGetSymbolAddress((void**)&pSemSyn, gSemSyn);

    const float qscale = 0.08838834764831845f;   // DH^-0.5
    dim3 blk(256);

    // 0-4: splits + convs (gemm_K lands at launch index 5 for ncu -s 5)
    split_f32<<<(B_ * S_ * D_) / 1024, blk>>>(enc, pEncH, pEncL, B_ * S_ * D_);   // 0
    split_f32<<<(D_ * D_) / 1024, blk>>>(wk, pWkH, pWkL, D_ * D_);                // 1
    split_f32<<<(D_ * D_) / 1024, blk>>>(wq, pWqH, pWqL, D_ * D_);                // 2
    conv_idx_kernel<<<1, blk>>>((const unsigned int*)to_sem_raw, B_ * L_, pToSem);// 3
    conv_idx_kernel<<<1, blk>>>((const unsigned int*)syn_raw,    B_ * S_, pSemSyn);//4

    // 5: K projection
    gemm_mma<<<dim3(8, 128, 1), blk>>>(
        pEncH, pEncL, pWkH, pWkL, bk, D_, D_, D_, nullptr, 1.f, 0, pK, nullptr,
        0, 0, 0, 0);
    // 6: Q projection (fused gather + scale)
    gemm_mma<<<dim3(8, 64, 1), blk>>>(
        pEncH, pEncL, pWqH, pWqL, bq, D_, D_, D_, pToSem, qscale, 0, pQ, nullptr,
        0, 0, 0, 0);

    // remaining prep
    split_f32<<<(D_ * D_) / 1024, blk>>>(wv, pWvH, pWvL, D_ * D_);
    split_f32<<<(D_ * D_) / 1024, blk>>>(wo, pWoH, pWoL, D_ * D_);
    split_f32<<<(D_ * CK_) / 1024, blk>>>(w_proj, pWpH, pWpL, D_ * CK_);
    split_f32<<<(1000 * WD_ + 1023) / 1024, blk>>>(type_emb, pTeH, pTeL, 1000 * WD_);
    conv_idx_kernel<<<1, blk>>>((const unsigned int*)typ_raw, B_ * L_, pToSemType);

    // fused type table: FT[1024, 1024] = type_emb @ Wp[:,1024:1280]^T (zero bias)
    gemm_mma<<<dim3(8, 8, 1), blk>>>(
        pTeH, pTeL, pWpH + D_, pWpL + D_, pZeroB, WD_, CK_, D_, nullptr, 1.f, 0,
        pFT, nullptr, 0, 0, 0, 0);

    // attention: scores + Z = P@enc (hi/lo)
    attn_kernel<<<B_ * L_, blk>>>(pQ, pK, enc, pSemSyn, pToSem, pZH, pZL);

    // ctx = Z_h @ Wv_h^T + bv_h, per head via blockIdx.z (N=128 each)
    gemm_mma<<<dim3(1, 64, H_), blk>>>(
        pZH, pZL, pWvH, pWvL, bv, D_, D_, D_, nullptr, 1.f, 1, pCtxH, pCtxL,
        (long)B_ * L_ * D_, (long)DH_ * D_, DH_, DH_);

    // O projection -> Out hi/lo planes
    gemm_mma<<<dim3(8, 64, 1), blk>>>(
        pCtxH, pCtxL, pWoH, pWoL, bo, D_, D_, D_, nullptr, 1.f, 1, pOutH, pOutL,
        0, 0, 0, 0);

    // final projection (K=1024 part) -> both fp32 outputs
    gemm_mma<<<dim3(8, 64, 1), blk>>>(
        pOutH, pOutL, pWpH, pWpL, b_proj, D_, CK_, D_, nullptr, 1.f, 2, out1, out2,
        0, 0, 0, 0);

    // add type-table contribution to both outputs
    add_table_kernel<<<B_ * L_, blk>>>(pToSemType, pFT, out1, out2);

    // root rows of out2
    root_fill_kernel<<<(B_ * D_) / 256, blk>>>(bias_root, out2);
}